// round 3
// baseline (speedup 1.0000x reference)
#include <cuda_runtime.h>

// rosa_emb_layer: B=8, T=2048, V=50257, C=768
// inputs: d_in[0] = idx (B,T) int32, d_in[1] = emb (V,C) float32
// output: (B,T,C) float32
//
// R2 redesign: matches require x[i]==x[j]; with random tokens, expected
// matching pairs per batch = T^2/(2V) ~ 42. So replace the O(T^2) compare
// scan with an O(T) smem hash chain (head[4096] + nxt[2048] linked lists
// keyed on token value). Each row walks its ~1.5-entry chain, filters
// j < i with exact value match, backward-extends, packs (L<<11)|j (exactly
// reproduces the L + j*1e-5 argmax with larger-j tie-break).
// Kernel 1 (8 CTAs): writes predicted token (or -1) to __device__ scratch.
// Kernel 2 (2048 CTAs): pure gather/zero epilogue -> 50MB L2-resident stores.

#define TT 2048
#define BB 8
#define CC 768
#define HSZ 4096   // hash slots (power of two)

__device__ int g_pred[BB * TT];   // predicted token id, -1 = no match

__global__ __launch_bounds__(1024, 1)
void rosa_match_kernel(const int* __restrict__ idx) {
    __shared__ int xs[TT];
    __shared__ int head[HSZ];
    __shared__ int nxt[TT];

    const int b   = blockIdx.x;
    const int tid = threadIdx.x;

    // Load batch token row (8 KB) + init hash heads.
    const int4* g = (const int4*)(idx + (size_t)b * TT);
    if (tid < TT / 4) ((int4*)xs)[tid] = g[tid];
    #pragma unroll
    for (int k = 0; k < HSZ / 1024; k++) head[tid + 1024 * k] = -1;
    __syncthreads();

    // Build per-value linked lists (order within a chain is irrelevant).
    #pragma unroll
    for (int k = 0; k < TT / 1024; k++) {
        const int i = tid + 1024 * k;
        const int h = xs[i] & (HSZ - 1);
        nxt[i] = atomicExch(&head[h], i);
    }
    __syncthreads();

    // For each row i: walk chain, backward-extend on true matches.
    #pragma unroll
    for (int k = 0; k < TT / 1024; k++) {
        const int i  = tid + 1024 * k;
        const int xi = xs[i];
        int best = 0;   // (L << 11) | j ; 0 == no match
        for (int j = head[xi & (HSZ - 1)]; j >= 0; j = nxt[j]) {
            if (j < i && xs[j] == xi) {
                int L = 1, t = 1;
                while (t <= j && xs[i - t] == xs[j - t]) { ++L; ++t; }
                const int packed = (L << 11) | j;
                if (packed > best) best = packed;
            }
        }
        int tok = -1;
        if (best >= (1 << 11)) {
            int pidx = (best & 2047) + 1;
            if (pidx > TT - 1) pidx = TT - 1;
            tok = xs[pidx];
        }
        g_pred[b * TT + i] = tok;
    }
}

__global__ __launch_bounds__(256, 8)
void rosa_gather_kernel(const float* __restrict__ emb,
                        float* __restrict__ out) {
    const int row  = blockIdx.x * 8 + (threadIdx.x >> 5);   // (b*T + i)
    const int lane = threadIdx.x & 31;
    const int tok  = g_pred[row];

    float4* orow = (float4*)(out + (size_t)row * CC);
    if (tok < 0) {
        const float4 z = make_float4(0.f, 0.f, 0.f, 0.f);
        #pragma unroll
        for (int k = 0; k < CC / 4 / 32; k++) orow[lane + 32 * k] = z;
    } else {
        const float4* erow = (const float4*)(emb + (size_t)tok * CC);
        #pragma unroll
        for (int k = 0; k < CC / 4 / 32; k++) orow[lane + 32 * k] = erow[lane + 32 * k];
    }
}

extern "C" void kernel_launch(void* const* d_in, const int* in_sizes, int n_in,
                              void* d_out, int out_size) {
    const int*   idx = (const int*)d_in[0];
    const float* emb = (const float*)d_in[1];
    float*       out = (float*)d_out;

    rosa_match_kernel<<<BB, 1024>>>(idx);
    rosa_gather_kernel<<<BB * TT / 8, 256>>>(emb, out);
}

// round 4
// speedup vs baseline: 1.4138x; 1.4138x over previous
#include <cuda_runtime.h>

// rosa_emb_layer: B=8, T=2048, V=50257, C=768
// inputs: d_in[0] = idx (B,T) int32, d_in[1] = emb (V,C) float32
// output: (B,T,C) float32
//
// R3: single fused kernel. Matches require x[i]==x[j]; random tokens =>
// expected matching pairs per batch ~ T^2/(2V) ~ 42, so an O(T) smem hash
// chain (head[4096]+nxt[2048]) replaces the O(T^2) scan. argmax of
// L + j*1e-5 (tie-break larger j) == integer max of (L<<11)|j.
// CTA = (batch, 32 rows): build hash, 32 threads walk chains -> pred[32] in
// smem, then 8 warps each stream 4 output rows (24 independent STG.128/lane)
// to hide store latency. ~99.98% of rows are zero-fill (no gather load).

#define TT 2048
#define BB 8
#define CC 768
#define HSZ 4096

__global__ __launch_bounds__(256)
void rosa_fused_kernel(const int* __restrict__ idx,
                       const float* __restrict__ emb,
                       float* __restrict__ out) {
    __shared__ int xs[TT];
    __shared__ int head[HSZ];
    __shared__ int nxt[TT];
    __shared__ int pred[32];

    const int b     = blockIdx.x >> 6;          // 64 CTAs per batch
    const int rbase = (blockIdx.x & 63) << 5;   // 32 rows per CTA
    const int tid   = threadIdx.x;

    // Load batch token row (8 KB) + init hash heads (int4 fills).
    const int4* g = (const int4*)(idx + (size_t)b * TT);
    ((int4*)xs)[tid]       = g[tid];
    ((int4*)xs)[tid + 256] = g[tid + 256];
    const int4 neg = make_int4(-1, -1, -1, -1);
    #pragma unroll
    for (int k = 0; k < HSZ / 4 / 256; k++) ((int4*)head)[tid + 256 * k] = neg;
    __syncthreads();

    // Build per-value linked lists (chain order irrelevant: we take a max).
    #pragma unroll
    for (int k = 0; k < TT / 256; k++) {
        const int i = tid + 256 * k;
        nxt[i] = atomicExch(&head[xs[i] & (HSZ - 1)], i);
    }
    __syncthreads();

    // 32 threads: walk chain for row rbase+tid, backward-extend on matches.
    if (tid < 32) {
        const int i  = rbase + tid;
        const int xi = xs[i];
        int best = 0;                            // (L<<11)|j ; 0 == no match
        for (int j = head[xi & (HSZ - 1)]; j >= 0; j = nxt[j]) {
            if (j < i && xs[j] == xi) {
                int L = 1, t = 1;
                while (t <= j && xs[i - t] == xs[j - t]) { ++L; ++t; }
                const int p = (L << 11) | j;
                if (p > best) best = p;
            }
        }
        int tok = -1;
        if (best >= (1 << 11)) {
            int pi = (best & 2047) + 1;
            if (pi > TT - 1) pi = TT - 1;
            tok = xs[pi];
        }
        pred[tid] = tok;
    }
    __syncthreads();

    // Store phase: warp w writes rows rbase+4w .. rbase+4w+3 (3 KB each).
    const int w = tid >> 5, lane = tid & 31;
    const int r0  = 4 * w;
    const int t0 = pred[r0], t1 = pred[r0 + 1], t2 = pred[r0 + 2], t3 = pred[r0 + 3];
    float4* o = (float4*)(out + ((size_t)b * TT + rbase + r0) * CC);
    const float4 z = make_float4(0.f, 0.f, 0.f, 0.f);

    if ((t0 | t1 | t2 | t3) < 0 && t0 < 0 && t1 < 0 && t2 < 0 && t3 < 0) {
        // Common case: all four rows zero -> 24 unrolled independent stores.
        #pragma unroll
        for (int k = 0; k < 4 * CC / 4 / 32; k++) o[lane + 32 * k] = z;
    } else {
        const int toks[4] = {t0, t1, t2, t3};
        #pragma unroll
        for (int r = 0; r < 4; r++) {
            float4* orow = o + (size_t)r * (CC / 4);
            if (toks[r] < 0) {
                #pragma unroll
                for (int k = 0; k < CC / 4 / 32; k++) orow[lane + 32 * k] = z;
            } else {
                const float4* e = (const float4*)(emb + (size_t)toks[r] * CC);
                #pragma unroll
                for (int k = 0; k < CC / 4 / 32; k++) orow[lane + 32 * k] = e[lane + 32 * k];
            }
        }
    }
}

extern "C" void kernel_launch(void* const* d_in, const int* in_sizes, int n_in,
                              void* d_out, int out_size) {
    const int*   idx = (const int*)d_in[0];
    const float* emb = (const float*)d_in[1];
    float*       out = (float*)d_out;

    rosa_fused_kernel<<<BB * 64, 256>>>(idx, emb, out);
}